// round 1
// baseline (speedup 1.0000x reference)
#include <cuda_runtime.h>
#include <math.h>

#define EPS 1e-5f

// Problem shape (fixed by the reference)
constexpr int B   = 4;
constexpr int H   = 8;
constexpr int SEQ = 4096;
constexpr int E   = 64;
constexpr int D   = 512;          // H*E
constexpr int BH  = B * H;        // 32
constexpr int L   = 64;           // chunk length
constexpr int C   = SEQ / L;      // 64 chunks per (b,h)
constexpr int M   = B * SEQ;      // 16384 GEMM rows

// Scratch (device globals — no allocation allowed)
__device__ float g_attn[(size_t)B * SEQ * D];   // [b, n, h*e]  (GEMM A matrix)
__device__ float g_ksum[(size_t)BH * C * E];    // chunk sums -> exclusive offsets
__device__ float g_vsum[(size_t)BH * C * E];

__device__ __forceinline__ float phi(float x) {
    // elu(x)+1 : x>0 -> x+1 ; x<=0 -> exp(x)
    return x > 0.f ? x + 1.f : __expf(x);
}

// ---------------------------------------------------------------------------
// Pass A: per-(bh, chunk) sums of phi(k) and v over the chunk's L rows.
// grid = BH*C blocks, 256 threads. Layout trick: offset of chunk = blk*L*E.
// ---------------------------------------------------------------------------
__global__ __launch_bounds__(256) void chunk_sums_kernel(
    const float* __restrict__ k, const float* __restrict__ v)
{
    const int blk = blockIdx.x;           // bh*C + c
    const int tid = threadIdx.x;
    const int e   = tid & 63;
    const int g   = tid >> 6;             // 0..3 row-groups of 16 rows
    const size_t base = (size_t)blk * (L * E);

    float sk = 0.f, sv = 0.f;
    #pragma unroll 4
    for (int i = g * 16; i < g * 16 + 16; ++i) {
        sk += phi(k[base + (size_t)i * E + e]);
        sv += v[base + (size_t)i * E + e];
    }
    __shared__ float shk[4][64], shv[4][64];
    shk[g][e] = sk; shv[g][e] = sv;
    __syncthreads();
    if (g == 0) {
        float tk = shk[0][e] + shk[1][e] + shk[2][e] + shk[3][e];
        float tv = shv[0][e] + shv[1][e] + shv[2][e] + shv[3][e];
        g_ksum[(size_t)blk * E + e] = tk;
        g_vsum[(size_t)blk * E + e] = tv;
    }
}

// ---------------------------------------------------------------------------
// Pass B: exclusive scan of the C chunk sums per (bh, e). grid = BH, 64 thr.
// ---------------------------------------------------------------------------
__global__ __launch_bounds__(64) void chunk_scan_kernel()
{
    const int bh = blockIdx.x;
    const int e  = threadIdx.x;
    float ak = 0.f, av = 0.f;
    size_t base = (size_t)bh * C * E + e;
    for (int c = 0; c < C; ++c) {
        size_t idx = base + (size_t)c * E;
        float tk = g_ksum[idx], tv = g_vsum[idx];
        g_ksum[idx] = ak;  g_vsum[idx] = av;
        ak += tk;          av += tv;
    }
}

// ---------------------------------------------------------------------------
// Pass C: per-(bh, chunk): in-chunk cumsum (seeded by exclusive offsets),
// per-row dot with phi(q), ratio, scaled vc written transposed into g_attn.
// grid = BH*C blocks, 256 threads.
// ---------------------------------------------------------------------------
__global__ __launch_bounds__(256) void attn_kernel(
    const float* __restrict__ q, const float* __restrict__ k,
    const float* __restrict__ v)
{
    const int blk = blockIdx.x;           // bh*C + c
    const int bh  = blk / C;
    const int c   = blk % C;
    const int b   = bh / H;
    const int h   = bh % H;
    const int tid = threadIdx.x;

    __shared__ float ks[L * E];   // 16 KB
    __shared__ float vs[L * E];   // 16 KB

    const size_t base = (size_t)blk * (L * E);

    // cooperative load + feature map
    #pragma unroll 4
    for (int i = tid; i < L * E; i += 256) {
        ks[i] = phi(k[base + i]);
        vs[i] = v[base + i];
    }
    __syncthreads();

    // serial in-chunk scan: thread t owns e-column t (conflict-free, stride E)
    if (tid < 64) {
        float ak = g_ksum[(size_t)blk * E + tid];
        float av = g_vsum[(size_t)blk * E + tid];
        #pragma unroll 8
        for (int i = 0; i < L; ++i) {
            ak += ks[i * E + tid]; ks[i * E + tid] = ak;
            av += vs[i * E + tid]; vs[i * E + tid] = av;
        }
    }
    __syncthreads();

    // per-row dot + ratio + write-out. 8 warps x 8 rows.
    const int w    = tid >> 5;
    const int lane = tid & 31;
    const int n0   = c * L;
    for (int i = w * (L / 8); i < (w + 1) * (L / 8); ++i) {
        float q0 = phi(q[base + (size_t)i * E + lane]);
        float q1 = phi(q[base + (size_t)i * E + lane + 32]);
        float p  = q0 * ks[i * E + lane] + q1 * ks[i * E + lane + 32];
        #pragma unroll
        for (int off = 16; off; off >>= 1)
            p += __shfl_xor_sync(0xffffffffu, p, off);
        float ratio = p / (p + EPS);
        size_t ob = ((size_t)b * SEQ + n0 + i) * D + (size_t)h * E;
        g_attn[ob + lane]      = ratio * vs[i * E + lane];
        g_attn[ob + lane + 32] = ratio * vs[i * E + lane + 32];
    }
}

// ---------------------------------------------------------------------------
// Pass D: out[M, D] = g_attn[M, D] @ W^T + bias.
// W is [D, D] row-major (j-th row = weights for output col j) -> both operands
// K-contiguous. Classic 128x128x8 fp32 SGEMM, 8x8 microtile, 256 threads.
// ---------------------------------------------------------------------------
constexpr int BM = 128, BN = 128, BK = 8;

__global__ __launch_bounds__(256) void gemm_kernel(
    const float* __restrict__ W, const float* __restrict__ bias,
    float* __restrict__ out)
{
    __shared__ float As[BK][BM];   // transposed A tile
    __shared__ float Bs[BK][BN];   // transposed W tile

    const int bn  = blockIdx.x;    // 0..D/BN-1  (4)
    const int bm  = blockIdx.y;    // 0..M/BM-1  (128)
    const int tid = threadIdx.x;
    const int tx  = tid & 15;      // 16 x 16 thread grid
    const int ty  = tid >> 4;

    const float* A  = g_attn + (size_t)bm * BM * D;
    const float* Bw = W      + (size_t)bn * BN * D;

    // loader mapping: each thread loads one float4 per tile per operand
    const int lr = tid >> 1;           // row within tile: 0..127
    const int lc = (tid & 1) * 4;      // k-offset: 0 or 4

    float acc[8][8] = {};

    for (int k0 = 0; k0 < D; k0 += BK) {
        float4 a4 = *(const float4*)(A  + (size_t)lr * D + k0 + lc);
        float4 b4 = *(const float4*)(Bw + (size_t)lr * D + k0 + lc);
        As[lc + 0][lr] = a4.x; As[lc + 1][lr] = a4.y;
        As[lc + 2][lr] = a4.z; As[lc + 3][lr] = a4.w;
        Bs[lc + 0][lr] = b4.x; Bs[lc + 1][lr] = b4.y;
        Bs[lc + 2][lr] = b4.z; Bs[lc + 3][lr] = b4.w;
        __syncthreads();

        #pragma unroll
        for (int kk = 0; kk < BK; ++kk) {
            float ra[8], rb[8];
            #pragma unroll
            for (int i = 0; i < 4; ++i) {
                ra[i]     = As[kk][ty * 8 + i];
                ra[i + 4] = As[kk][ty * 8 + 4 + i];
                rb[i]     = Bs[kk][tx * 8 + i];
                rb[i + 4] = Bs[kk][tx * 8 + 4 + i];
            }
            #pragma unroll
            for (int i = 0; i < 8; ++i)
                #pragma unroll
                for (int j = 0; j < 8; ++j)
                    acc[i][j] += ra[i] * rb[j];
        }
        __syncthreads();
    }

    // epilogue: add bias, write 8x8 per thread
    #pragma unroll
    for (int i = 0; i < 8; ++i) {
        const int row = bm * BM + ty * 8 + i;
        float* orow = out + (size_t)row * D + bn * BN + tx * 8;
        const float* brow = bias + bn * BN + tx * 8;
        #pragma unroll
        for (int j = 0; j < 8; ++j)
            orow[j] = acc[i][j] + brow[j];
    }
}

// ---------------------------------------------------------------------------
extern "C" void kernel_launch(void* const* d_in, const int* in_sizes, int n_in,
                              void* d_out, int out_size)
{
    const float* q    = (const float*)d_in[0];
    const float* k    = (const float*)d_in[1];
    const float* v    = (const float*)d_in[2];
    // d_in[3] = mask (unused)
    const float* W    = (const float*)d_in[4];
    const float* bias = (const float*)d_in[5];
    float* out = (float*)d_out;

    chunk_sums_kernel<<<BH * C, 256>>>(k, v);
    chunk_scan_kernel<<<BH, 64>>>();
    attn_kernel<<<BH * C, 256>>>(q, k, v);
    dim3 grid(D / BN, M / BM);   // (4, 128)
    gemm_kernel<<<grid, 256>>>(W, bias, out);
}

// round 4
// speedup vs baseline: 1.7968x; 1.7968x over previous
#include <cuda_runtime.h>
#include <cuda_bf16.h>
#include <cstdint>

#define EPS 1e-5f

// Problem shape (fixed by the reference)
constexpr int B   = 4;
constexpr int H   = 8;
constexpr int SEQ = 4096;
constexpr int E   = 64;
constexpr int D   = 512;          // H*E
constexpr int BH  = B * H;        // 32
constexpr int L   = 64;           // chunk length (attn passes)
constexpr int C   = SEQ / L;      // 64 chunks per (b,h)
constexpr int M   = B * SEQ;      // 16384 GEMM rows

// Scratch (device globals — no allocation allowed)
__device__ __nv_bfloat16 g_Ahi[(size_t)M * D];
__device__ __nv_bfloat16 g_Alo[(size_t)M * D];
__device__ __nv_bfloat16 g_Whi[(size_t)D * D];
__device__ __nv_bfloat16 g_Wlo[(size_t)D * D];
__device__ float g_ksum[(size_t)BH * C * E];
__device__ float g_vsum[(size_t)BH * C * E];

__device__ __forceinline__ float phi(float x) {
    return x > 0.f ? x + 1.f : __expf(x);
}

__device__ __forceinline__ uint32_t smem_u32(const void* p) {
    uint32_t a;
    asm("{ .reg .u64 t; cvta.to.shared.u64 t, %1; cvt.u32.u64 %0, t; }"
        : "=r"(a) : "l"(p));
    return a;
}

// ---------------------------------------------------------------------------
// Pass A: per-(bh, chunk) sums of phi(k) and v.
// ---------------------------------------------------------------------------
__global__ __launch_bounds__(256) void chunk_sums_kernel(
    const float* __restrict__ k, const float* __restrict__ v)
{
    const int blk = blockIdx.x;
    const int tid = threadIdx.x;
    const int e   = tid & 63;
    const int g   = tid >> 6;
    const size_t base = (size_t)blk * (L * E);

    float sk = 0.f, sv = 0.f;
    #pragma unroll 4
    for (int i = g * 16; i < g * 16 + 16; ++i) {
        sk += phi(k[base + (size_t)i * E + e]);
        sv += v[base + (size_t)i * E + e];
    }
    __shared__ float shk[4][64], shv[4][64];
    shk[g][e] = sk; shv[g][e] = sv;
    __syncthreads();
    if (g == 0) {
        g_ksum[(size_t)blk * E + e] = shk[0][e] + shk[1][e] + shk[2][e] + shk[3][e];
        g_vsum[(size_t)blk * E + e] = shv[0][e] + shv[1][e] + shv[2][e] + shv[3][e];
    }
}

// ---------------------------------------------------------------------------
// Pass B: exclusive scan of chunk sums per (bh, e).
// ---------------------------------------------------------------------------
__global__ __launch_bounds__(64) void chunk_scan_kernel()
{
    const int bh = blockIdx.x;
    const int e  = threadIdx.x;
    float ak = 0.f, av = 0.f;
    size_t base = (size_t)bh * C * E + e;
    for (int c = 0; c < C; ++c) {
        size_t idx = base + (size_t)c * E;
        float tk = g_ksum[idx], tv = g_vsum[idx];
        g_ksum[idx] = ak;  g_vsum[idx] = av;
        ak += tk;          av += tv;
    }
}

// ---------------------------------------------------------------------------
// Pass C: in-chunk cumsum + per-row dot + ratio; emit A as bf16 hi/lo pair.
// ---------------------------------------------------------------------------
__global__ __launch_bounds__(256) void attn_kernel(
    const float* __restrict__ q, const float* __restrict__ k,
    const float* __restrict__ v)
{
    const int blk = blockIdx.x;
    const int bh  = blk / C;
    const int c   = blk % C;
    const int b   = bh / H;
    const int h   = bh % H;
    const int tid = threadIdx.x;

    __shared__ float ks[L * E];
    __shared__ float vs[L * E];

    const size_t base = (size_t)blk * (L * E);

    #pragma unroll 4
    for (int i = tid; i < L * E; i += 256) {
        ks[i] = phi(k[base + i]);
        vs[i] = v[base + i];
    }
    __syncthreads();

    if (tid < 64) {
        float ak = g_ksum[(size_t)blk * E + tid];
        float av = g_vsum[(size_t)blk * E + tid];
        #pragma unroll 8
        for (int i = 0; i < L; ++i) {
            ak += ks[i * E + tid]; ks[i * E + tid] = ak;
            av += vs[i * E + tid]; vs[i * E + tid] = av;
        }
    }
    __syncthreads();

    const int w    = tid >> 5;
    const int lane = tid & 31;
    const int n0   = c * L;
    for (int i = w * (L / 8); i < (w + 1) * (L / 8); ++i) {
        float q0 = phi(q[base + (size_t)i * E + lane]);
        float q1 = phi(q[base + (size_t)i * E + lane + 32]);
        float p  = q0 * ks[i * E + lane] + q1 * ks[i * E + lane + 32];
        #pragma unroll
        for (int off = 16; off; off >>= 1)
            p += __shfl_xor_sync(0xffffffffu, p, off);
        float ratio = p / (p + EPS);
        size_t ob = ((size_t)b * SEQ + n0 + i) * D + (size_t)h * E;

        float x0 = ratio * vs[i * E + lane];
        float x1 = ratio * vs[i * E + lane + 32];
        __nv_bfloat16 h0 = __float2bfloat16(x0);
        __nv_bfloat16 h1 = __float2bfloat16(x1);
        g_Ahi[ob + lane]      = h0;
        g_Ahi[ob + lane + 32] = h1;
        g_Alo[ob + lane]      = __float2bfloat16(x0 - __bfloat162float(h0));
        g_Alo[ob + lane + 32] = __float2bfloat16(x1 - __bfloat162float(h1));
    }
}

// ---------------------------------------------------------------------------
// Pass W: split W into bf16 hi/lo.
// ---------------------------------------------------------------------------
__global__ __launch_bounds__(256) void wsplit_kernel(const float* __restrict__ W)
{
    int i = blockIdx.x * 256 + threadIdx.x;
    float w = W[i];
    __nv_bfloat16 hi = __float2bfloat16(w);
    g_Whi[i] = hi;
    g_Wlo[i] = __float2bfloat16(w - __bfloat162float(hi));
}

// ---------------------------------------------------------------------------
// Pass D: mma.sync bf16-split GEMM. out[M,512] = A @ W^T + bias
// BM=128, BN=128, BK=32, 8 warps (4m x 2n), warp tile 32x64.
// 3 split terms: Ahi*Bhi + Ahi*Blo + Alo*Bhi, fp32 accum in registers.
// W is [n][k] row-major -> B fragment needs NON-trans ldmatrix (lane l gets
// W[l/4][2*(l%4)..+1] = B[k][n] col fragment).
// SMEM rows padded to 80B -> conflict-free 8-row ldmatrix.
// cp.async double-buffered (2 x 40960 B).
// ---------------------------------------------------------------------------
constexpr int BK   = 32;
constexpr int NK   = D / BK;        // 16
constexpr int RS   = 80;            // smem row stride (bytes) for 64B of data
constexpr int MTX  = 128 * RS;      // 10240 bytes per matrix region
constexpr int STG  = 4 * MTX;       // Ah | Al | Bh | Bl per stage
constexpr int GEMM_DSMEM = 2 * STG; // 81920

__device__ __forceinline__ void cp16(uint32_t dst, const void* src) {
    asm volatile("cp.async.cg.shared.global [%0], [%1], 16;"
                 :: "r"(dst), "l"(src) : "memory");
}
__device__ __forceinline__ void cp_commit() {
    asm volatile("cp.async.commit_group;" ::: "memory");
}
template<int N> __device__ __forceinline__ void cp_wait() {
    asm volatile("cp.async.wait_group %0;" :: "n"(N) : "memory");
}
__device__ __forceinline__ void ldsm4(uint32_t* r, uint32_t a) {
    asm volatile("ldmatrix.sync.aligned.m8n8.x4.shared.b16 {%0,%1,%2,%3}, [%4];"
                 : "=r"(r[0]), "=r"(r[1]), "=r"(r[2]), "=r"(r[3]) : "r"(a));
}
__device__ __forceinline__ void mma16816(float* c, const uint32_t* a,
                                         uint32_t b0, uint32_t b1) {
    asm volatile(
        "mma.sync.aligned.m16n8k16.row.col.f32.bf16.bf16.f32 "
        "{%0,%1,%2,%3}, {%4,%5,%6,%7}, {%8,%9}, {%0,%1,%2,%3};"
        : "+f"(c[0]), "+f"(c[1]), "+f"(c[2]), "+f"(c[3])
        : "r"(a[0]), "r"(a[1]), "r"(a[2]), "r"(a[3]), "r"(b0), "r"(b1));
}

__global__ __launch_bounds__(256, 1) void gemm_mma_kernel(
    const float* __restrict__ bias, float* __restrict__ out)
{
    extern __shared__ char sm[];
    const int tid  = threadIdx.x;
    const int lane = tid & 31;
    const int wid  = tid >> 5;
    const int wm   = wid & 3;       // 0..3: 32-row slab
    const int wn   = wid >> 2;      // 0..1: 64-col slab
    const int bn   = blockIdx.x;    // 0..3
    const int bm   = blockIdx.y;    // 0..127
    const uint32_t sbase = smem_u32(sm);

    // cp.async loader mapping: 2 chunks/thread per matrix region
    const int lj0 = tid, lj1 = tid + 256;   // j in [0,512): r=j>>2, c=j&3

    auto load_stage = [&](int s, int kt) {
        const int k0 = kt * BK;
        const uint32_t d0 = sbase + s * STG;
        #pragma unroll
        for (int hh = 0; hh < 2; ++hh) {
            const int j = hh ? lj1 : lj0;
            const int r = j >> 2, c = j & 3;
            const uint32_t so = (uint32_t)(r * RS + c * 16);
            const size_t ga = (size_t)(bm * 128 + r) * D + k0 + c * 8;
            const size_t gb = (size_t)(bn * 128 + r) * D + k0 + c * 8;
            cp16(d0 + 0 * MTX + so, g_Ahi + ga);
            cp16(d0 + 1 * MTX + so, g_Alo + ga);
            cp16(d0 + 2 * MTX + so, g_Whi + gb);
            cp16(d0 + 3 * MTX + so, g_Wlo + gb);
        }
    };

    // ldmatrix per-lane addressing: row = lane&15, k-half = lane>>4
    const int lrow = lane & 15, lkh = lane >> 4;
    const uint32_t aoff = (uint32_t)((wm * 32 + lrow) * RS + lkh * 16);
    const uint32_t boff = (uint32_t)(2 * MTX + (wn * 64 + lrow) * RS + lkh * 16);

    float acc[2][8][4] = {};

    load_stage(0, 0);
    cp_commit();

    for (int kt = 0; kt < NK; ++kt) {
        const int s = kt & 1;
        if (kt + 1 < NK) { load_stage(s ^ 1, kt + 1); cp_commit(); cp_wait<1>(); }
        else             { cp_wait<0>(); }
        __syncthreads();

        const uint32_t st0 = sbase + s * STG;
        #pragma unroll
        for (int st = 0; st < 2; ++st) {        // two k16 steps per BK=32
            uint32_t ah[2][4], al[2][4], bh[4][4], bl[4][4];
            #pragma unroll
            for (int mi = 0; mi < 2; ++mi) {
                const uint32_t a = st0 + aoff + mi * (16 * RS) + st * 32;
                ldsm4(ah[mi], a);
                ldsm4(al[mi], a + MTX);
            }
            #pragma unroll
            for (int nt = 0; nt < 4; ++nt) {
                const uint32_t a = st0 + boff + nt * (16 * RS) + st * 32;
                ldsm4(bh[nt], a);           // NON-trans: W is [n][k] row-major
                ldsm4(bl[nt], a + MTX);
            }
            #pragma unroll
            for (int mi = 0; mi < 2; ++mi)
                #pragma unroll
                for (int nt = 0; nt < 4; ++nt) {
                    mma16816(acc[mi][nt*2+0], ah[mi], bh[nt][0], bh[nt][2]);
                    mma16816(acc[mi][nt*2+1], ah[mi], bh[nt][1], bh[nt][3]);
                    mma16816(acc[mi][nt*2+0], ah[mi], bl[nt][0], bl[nt][2]);
                    mma16816(acc[mi][nt*2+1], ah[mi], bl[nt][1], bl[nt][3]);
                    mma16816(acc[mi][nt*2+0], al[mi], bh[nt][0], bh[nt][2]);
                    mma16816(acc[mi][nt*2+1], al[mi], bh[nt][1], bh[nt][3]);
                }
        }
        __syncthreads();
    }

    // Epilogue: c-frag rows g, g+8; cols 2*tig, 2*tig+1
    const int g   = lane >> 2;
    const int tig = lane & 3;
    #pragma unroll
    for (int mi = 0; mi < 2; ++mi) {
        const int row0 = bm * 128 + wm * 32 + mi * 16 + g;
        #pragma unroll
        for (int nt = 0; nt < 4; ++nt)
            #pragma unroll
            for (int nh = 0; nh < 2; ++nh) {
                const float* a4 = acc[mi][nt * 2 + nh];
                const int col = bn * 128 + wn * 64 + nt * 16 + nh * 8 + tig * 2;
                const float2 bv = *(const float2*)(bias + col);
                float2 o0 = { a4[0] + bv.x, a4[1] + bv.y };
                float2 o1 = { a4[2] + bv.x, a4[3] + bv.y };
                *(float2*)(out + (size_t)row0 * D + col)       = o0;
                *(float2*)(out + (size_t)(row0 + 8) * D + col) = o1;
            }
    }
}

// ---------------------------------------------------------------------------
extern "C" void kernel_launch(void* const* d_in, const int* in_sizes, int n_in,
                              void* d_out, int out_size)
{
    const float* q    = (const float*)d_in[0];
    const float* k    = (const float*)d_in[1];
    const float* v    = (const float*)d_in[2];
    // d_in[3] = mask (unused)
    const float* W    = (const float*)d_in[4];
    const float* bias = (const float*)d_in[5];
    float* out = (float*)d_out;

    // idempotent, called every launch (no static guards)
    cudaFuncSetAttribute(gemm_mma_kernel,
                         cudaFuncAttributeMaxDynamicSharedMemorySize, GEMM_DSMEM);

    chunk_sums_kernel<<<BH * C, 256>>>(k, v);
    chunk_scan_kernel<<<BH, 64>>>();
    attn_kernel<<<BH * C, 256>>>(q, k, v);
    wsplit_kernel<<<(D * D) / 256, 256>>>(W);
    gemm_mma_kernel<<<dim3(4, 128), 256, GEMM_DSMEM>>>(bias, out);
}

// round 5
// speedup vs baseline: 1.9259x; 1.0719x over previous
#include <cuda_runtime.h>
#include <cuda_bf16.h>
#include <cstdint>

#define EPS 1e-5f

// Problem shape (fixed by the reference)
constexpr int B   = 4;
constexpr int H   = 8;
constexpr int SEQ = 4096;
constexpr int E   = 64;
constexpr int D   = 512;          // H*E
constexpr int BH  = B * H;        // 32
constexpr int L   = 64;           // chunk length (attn passes)
constexpr int C   = SEQ / L;      // 64 chunks per (b,h)
constexpr int M   = B * SEQ;      // 16384 GEMM rows

// Scratch (device globals — no allocation allowed)
__device__ __nv_bfloat16 g_Ahi[(size_t)M * D];
__device__ __nv_bfloat16 g_Alo[(size_t)M * D];
__device__ __nv_bfloat16 g_Whi[(size_t)D * D];
__device__ __nv_bfloat16 g_Wlo[(size_t)D * D];
__device__ float g_ksum[(size_t)BH * C * E];
__device__ float g_vsum[(size_t)BH * C * E];

__device__ __forceinline__ float phi(float x) {
    return x > 0.f ? x + 1.f : __expf(x);
}

__device__ __forceinline__ uint32_t smem_u32(const void* p) {
    uint32_t a;
    asm("{ .reg .u64 t; cvta.to.shared.u64 t, %1; cvt.u32.u64 %0, t; }"
        : "=r"(a) : "l"(p));
    return a;
}

// ---------------------------------------------------------------------------
// Pass A: per-(bh, chunk) sums of phi(k) and v.
// ---------------------------------------------------------------------------
__global__ __launch_bounds__(256) void chunk_sums_kernel(
    const float* __restrict__ k, const float* __restrict__ v)
{
    const int blk = blockIdx.x;
    const int tid = threadIdx.x;
    const int e   = tid & 63;
    const int g   = tid >> 6;
    const size_t base = (size_t)blk * (L * E);

    float sk = 0.f, sv = 0.f;
    #pragma unroll 4
    for (int i = g * 16; i < g * 16 + 16; ++i) {
        sk += phi(k[base + (size_t)i * E + e]);
        sv += v[base + (size_t)i * E + e];
    }
    __shared__ float shk[4][64], shv[4][64];
    shk[g][e] = sk; shv[g][e] = sv;
    __syncthreads();
    if (g == 0) {
        g_ksum[(size_t)blk * E + e] = shk[0][e] + shk[1][e] + shk[2][e] + shk[3][e];
        g_vsum[(size_t)blk * E + e] = shv[0][e] + shv[1][e] + shv[2][e] + shv[3][e];
    }
}

// ---------------------------------------------------------------------------
// Pass B: exclusive scan of chunk sums per (bh, e).
// ---------------------------------------------------------------------------
__global__ __launch_bounds__(64) void chunk_scan_kernel()
{
    const int bh = blockIdx.x;
    const int e  = threadIdx.x;
    float ak = 0.f, av = 0.f;
    size_t base = (size_t)bh * C * E + e;
    for (int c = 0; c < C; ++c) {
        size_t idx = base + (size_t)c * E;
        float tk = g_ksum[idx], tv = g_vsum[idx];
        g_ksum[idx] = ak;  g_vsum[idx] = av;
        ak += tk;          av += tv;
    }
}

// ---------------------------------------------------------------------------
// Pass C: in-chunk cumsum + per-row dot + ratio; emit A as bf16 hi/lo pair.
// Lane owns e = {2*lane, 2*lane+1} so outputs store as one bf162 (coalesced).
// ---------------------------------------------------------------------------
__global__ __launch_bounds__(256) void attn_kernel(
    const float* __restrict__ q, const float* __restrict__ k,
    const float* __restrict__ v)
{
    const int blk = blockIdx.x;
    const int bh  = blk / C;
    const int c   = blk % C;
    const int b   = bh / H;
    const int h   = bh % H;
    const int tid = threadIdx.x;

    __shared__ float ks[L * E];
    __shared__ float vs[L * E];

    const size_t base = (size_t)blk * (L * E);

    // cooperative vectorized load + feature map
    #pragma unroll
    for (int i = tid; i < (L * E) / 4; i += 256) {
        float4 kk = ((const float4*)(k + base))[i];
        kk.x = phi(kk.x); kk.y = phi(kk.y); kk.z = phi(kk.z); kk.w = phi(kk.w);
        ((float4*)ks)[i] = kk;
        ((float4*)vs)[i] = ((const float4*)(v + base))[i];
    }
    __syncthreads();

    if (tid < 64) {
        float ak = g_ksum[(size_t)blk * E + tid];
        float av = g_vsum[(size_t)blk * E + tid];
        #pragma unroll 8
        for (int i = 0; i < L; ++i) {
            ak += ks[i * E + tid]; ks[i * E + tid] = ak;
            av += vs[i * E + tid]; vs[i * E + tid] = av;
        }
    }
    __syncthreads();

    const int w    = tid >> 5;
    const int lane = tid & 31;
    const int e0   = lane * 2;
    const int n0   = c * L;
    for (int i = w * (L / 8); i < (w + 1) * (L / 8); ++i) {
        const float2 qq = *(const float2*)(q + base + (size_t)i * E + e0);
        float p = phi(qq.x) * ks[i * E + e0] + phi(qq.y) * ks[i * E + e0 + 1];
        #pragma unroll
        for (int off = 16; off; off >>= 1)
            p += __shfl_xor_sync(0xffffffffu, p, off);
        float ratio = p / (p + EPS);
        size_t ob = ((size_t)b * SEQ + n0 + i) * D + (size_t)h * E + e0;

        float x0 = ratio * vs[i * E + e0];
        float x1 = ratio * vs[i * E + e0 + 1];
        __nv_bfloat16 h0 = __float2bfloat16(x0);
        __nv_bfloat16 h1 = __float2bfloat16(x1);
        __nv_bfloat162 hi2; hi2.x = h0; hi2.y = h1;
        __nv_bfloat162 lo2;
        lo2.x = __float2bfloat16(x0 - __bfloat162float(h0));
        lo2.y = __float2bfloat16(x1 - __bfloat162float(h1));
        *(__nv_bfloat162*)(g_Ahi + ob) = hi2;
        *(__nv_bfloat162*)(g_Alo + ob) = lo2;
    }
}

// ---------------------------------------------------------------------------
// Pass W: split W into bf16 hi/lo.
// ---------------------------------------------------------------------------
__global__ __launch_bounds__(256) void wsplit_kernel(const float* __restrict__ W)
{
    int i = blockIdx.x * 256 + threadIdx.x;
    float w = W[i];
    __nv_bfloat16 hi = __float2bfloat16(w);
    g_Whi[i] = hi;
    g_Wlo[i] = __float2bfloat16(w - __bfloat162float(hi));
}

// ---------------------------------------------------------------------------
// Pass D: mma.sync bf16-split GEMM. out[M,512] = A @ W^T + bias
// BM=128, BN=256, BK=32, 512 threads / 16 warps (4m x 4n), warp tile 32x64.
// 3 split terms: Ahi*Bhi + Ahi*Blo + Alo*Bhi, fp32 accum in registers.
// W is [n][k] row-major -> B fragment uses NON-trans ldmatrix.
// SMEM rows padded to 80B -> conflict-free ldmatrix. 2-stage cp.async.
// ---------------------------------------------------------------------------
constexpr int BK   = 32;
constexpr int NK   = D / BK;          // 16
constexpr int RS   = 80;              // smem row stride (bytes) for 64B of data
constexpr int MTXA = 128 * RS;        // 10240
constexpr int MTXB = 256 * RS;        // 20480
constexpr int STG  = 2 * MTXA + 2 * MTXB;  // 61440: Ah | Al | Bh | Bl
constexpr int GEMM_DSMEM = 2 * STG;   // 122880

__device__ __forceinline__ void cp16(uint32_t dst, const void* src) {
    asm volatile("cp.async.cg.shared.global [%0], [%1], 16;"
                 :: "r"(dst), "l"(src) : "memory");
}
__device__ __forceinline__ void cp_commit() {
    asm volatile("cp.async.commit_group;" ::: "memory");
}
template<int N> __device__ __forceinline__ void cp_wait() {
    asm volatile("cp.async.wait_group %0;" :: "n"(N) : "memory");
}
__device__ __forceinline__ void ldsm4(uint32_t* r, uint32_t a) {
    asm volatile("ldmatrix.sync.aligned.m8n8.x4.shared.b16 {%0,%1,%2,%3}, [%4];"
                 : "=r"(r[0]), "=r"(r[1]), "=r"(r[2]), "=r"(r[3]) : "r"(a));
}
__device__ __forceinline__ void mma16816(float* c, const uint32_t* a,
                                         uint32_t b0, uint32_t b1) {
    asm volatile(
        "mma.sync.aligned.m16n8k16.row.col.f32.bf16.bf16.f32 "
        "{%0,%1,%2,%3}, {%4,%5,%6,%7}, {%8,%9}, {%0,%1,%2,%3};"
        : "+f"(c[0]), "+f"(c[1]), "+f"(c[2]), "+f"(c[3])
        : "r"(a[0]), "r"(a[1]), "r"(a[2]), "r"(a[3]), "r"(b0), "r"(b1));
}

__global__ __launch_bounds__(512, 1) void gemm_mma_kernel(
    const float* __restrict__ bias, float* __restrict__ out)
{
    extern __shared__ char sm[];
    const int tid  = threadIdx.x;
    const int lane = tid & 31;
    const int wid  = tid >> 5;      // 0..15
    const int wm   = wid & 3;       // 0..3: 32-row slab
    const int wn   = wid >> 2;      // 0..3: 64-col slab
    const int bn   = blockIdx.x;    // 0..1
    const int bm   = blockIdx.y;    // 0..127
    const uint32_t sbase = smem_u32(sm);

    auto load_stage = [&](int s, int kt) {
        const int k0 = kt * BK;
        const uint32_t d0 = sbase + s * STG;
        // A: 512 float4 chunks (128 rows x 4), one per thread per matrix
        {
            const int r = tid >> 2, c = tid & 3;
            const uint32_t so = (uint32_t)(r * RS + c * 16);
            const size_t ga = (size_t)(bm * 128 + r) * D + k0 + c * 8;
            cp16(d0 + so,        g_Ahi + ga);
            cp16(d0 + MTXA + so, g_Alo + ga);
        }
        // B: 1024 chunks (256 rows x 4), two per thread per matrix
        #pragma unroll
        for (int hh = 0; hh < 2; ++hh) {
            const int j = tid + hh * 512;
            const int r = j >> 2, c = j & 3;
            const uint32_t so = (uint32_t)(r * RS + c * 16);
            const size_t gb = (size_t)(bn * 256 + r) * D + k0 + c * 8;
            cp16(d0 + 2 * MTXA + so,        g_Whi + gb);
            cp16(d0 + 2 * MTXA + MTXB + so, g_Wlo + gb);
        }
    };

    // ldmatrix per-lane addressing: row = lane&15, k-half = lane>>4
    const int lrow = lane & 15, lkh = lane >> 4;
    const uint32_t aoff = (uint32_t)((wm * 32 + lrow) * RS + lkh * 16);
    const uint32_t boff = (uint32_t)(2 * MTXA + (wn * 64 + lrow) * RS + lkh * 16);

    float acc[2][8][4] = {};

    load_stage(0, 0);
    cp_commit();

    for (int kt = 0; kt < NK; ++kt) {
        const int s = kt & 1;
        if (kt + 1 < NK) { load_stage(s ^ 1, kt + 1); cp_commit(); cp_wait<1>(); }
        else             { cp_wait<0>(); }
        __syncthreads();

        const uint32_t st0 = sbase + s * STG;
        #pragma unroll
        for (int st = 0; st < 2; ++st) {        // two k16 steps per BK=32
            uint32_t ah[2][4], al[2][4], bh[4][4], bl[4][4];
            #pragma unroll
            for (int mi = 0; mi < 2; ++mi) {
                const uint32_t a = st0 + aoff + mi * (16 * RS) + st * 32;
                ldsm4(ah[mi], a);
                ldsm4(al[mi], a + MTXA);
            }
            #pragma unroll
            for (int nt = 0; nt < 4; ++nt) {
                const uint32_t a = st0 + boff + nt * (16 * RS) + st * 32;
                ldsm4(bh[nt], a);           // NON-trans: W is [n][k] row-major
                ldsm4(bl[nt], a + MTXB);
            }
            #pragma unroll
            for (int mi = 0; mi < 2; ++mi)
                #pragma unroll
                for (int nt = 0; nt < 4; ++nt) {
                    mma16816(acc[mi][nt*2+0], ah[mi], bh[nt][0], bh[nt][2]);
                    mma16816(acc[mi][nt*2+1], ah[mi], bh[nt][1], bh[nt][3]);
                    mma16816(acc[mi][nt*2+0], ah[mi], bl[nt][0], bl[nt][2]);
                    mma16816(acc[mi][nt*2+1], ah[mi], bl[nt][1], bl[nt][3]);
                    mma16816(acc[mi][nt*2+0], al[mi], bh[nt][0], bh[nt][2]);
                    mma16816(acc[mi][nt*2+1], al[mi], bh[nt][1], bh[nt][3]);
                }
        }
        __syncthreads();
    }

    // Epilogue: c-frag rows g, g+8; cols 2*tig, 2*tig+1
    const int g   = lane >> 2;
    const int tig = lane & 3;
    #pragma unroll
    for (int mi = 0; mi < 2; ++mi) {
        const int row0 = bm * 128 + wm * 32 + mi * 16 + g;
        #pragma unroll
        for (int nt = 0; nt < 4; ++nt)
            #pragma unroll
            for (int nh = 0; nh < 2; ++nh) {
                const float* a4 = acc[mi][nt * 2 + nh];
                const int col = bn * 256 + wn * 64 + nt * 16 + nh * 8 + tig * 2;
                const float2 bv = *(const float2*)(bias + col);
                float2 o0 = { a4[0] + bv.x, a4[1] + bv.y };
                float2 o1 = { a4[2] + bv.x, a4[3] + bv.y };
                *(float2*)(out + (size_t)row0 * D + col)       = o0;
                *(float2*)(out + (size_t)(row0 + 8) * D + col) = o1;
            }
    }
}

// ---------------------------------------------------------------------------
extern "C" void kernel_launch(void* const* d_in, const int* in_sizes, int n_in,
                              void* d_out, int out_size)
{
    const float* q    = (const float*)d_in[0];
    const float* k    = (const float*)d_in[1];
    const float* v    = (const float*)d_in[2];
    // d_in[3] = mask (unused)
    const float* W    = (const float*)d_in[4];
    const float* bias = (const float*)d_in[5];
    float* out = (float*)d_out;

    // idempotent, called every launch (no static guards)
    cudaFuncSetAttribute(gemm_mma_kernel,
                         cudaFuncAttributeMaxDynamicSharedMemorySize, GEMM_DSMEM);

    chunk_sums_kernel<<<BH * C, 256>>>(k, v);
    chunk_scan_kernel<<<BH, 64>>>();
    attn_kernel<<<BH * C, 256>>>(q, k, v);
    wsplit_kernel<<<(D * D) / 256, 256>>>(W);
    gemm_mma_kernel<<<dim3(2, 128), 512, GEMM_DSMEM>>>(bias, out);
}

// round 6
// speedup vs baseline: 2.3367x; 1.2133x over previous
#include <cuda_runtime.h>
#include <cuda_bf16.h>
#include <cuda_fp16.h>
#include <cstdint>

#define EPS 1e-5f

// Problem shape (fixed by the reference)
constexpr int B   = 4;
constexpr int H   = 8;
constexpr int SEQ = 4096;
constexpr int E   = 64;
constexpr int D   = 512;          // H*E
constexpr int BH  = B * H;        // 32
constexpr int L   = 64;           // chunk length (attn passes)
constexpr int C   = SEQ / L;      // 64 chunks per (b,h)
constexpr int M   = B * SEQ;      // 16384 GEMM rows

// Scratch (device globals — no allocation allowed)
__device__ __half g_Af [(size_t)M * D];    // A in fp16 (single precision level)
__device__ __half g_Whi[(size_t)D * D];    // W fp16 hi
__device__ __half g_Wlo[(size_t)D * D];    // W fp16 lo (residual)
__device__ float g_ksum[(size_t)BH * C * E];
__device__ float g_vsum[(size_t)BH * C * E];

__device__ __forceinline__ float phi(float x) {
    return x > 0.f ? x + 1.f : __expf(x);
}

__device__ __forceinline__ uint32_t smem_u32(const void* p) {
    uint32_t a;
    asm("{ .reg .u64 t; cvta.to.shared.u64 t, %1; cvt.u32.u64 %0, t; }"
        : "=r"(a) : "l"(p));
    return a;
}

// ---------------------------------------------------------------------------
// Pass A: per-(bh, chunk) sums of phi(k) and v.
// ---------------------------------------------------------------------------
__global__ __launch_bounds__(256) void chunk_sums_kernel(
    const float* __restrict__ k, const float* __restrict__ v)
{
    const int blk = blockIdx.x;
    const int tid = threadIdx.x;
    const int e   = tid & 63;
    const int g   = tid >> 6;
    const size_t base = (size_t)blk * (L * E);

    float sk = 0.f, sv = 0.f;
    #pragma unroll 4
    for (int i = g * 16; i < g * 16 + 16; ++i) {
        sk += phi(k[base + (size_t)i * E + e]);
        sv += v[base + (size_t)i * E + e];
    }
    __shared__ float shk[4][64], shv[4][64];
    shk[g][e] = sk; shv[g][e] = sv;
    __syncthreads();
    if (g == 0) {
        g_ksum[(size_t)blk * E + e] = shk[0][e] + shk[1][e] + shk[2][e] + shk[3][e];
        g_vsum[(size_t)blk * E + e] = shv[0][e] + shv[1][e] + shv[2][e] + shv[3][e];
    }
}

// ---------------------------------------------------------------------------
// Pass B: exclusive scan of chunk sums per (bh, e).
// ---------------------------------------------------------------------------
__global__ __launch_bounds__(64) void chunk_scan_kernel()
{
    const int bh = blockIdx.x;
    const int e  = threadIdx.x;
    float ak = 0.f, av = 0.f;
    size_t base = (size_t)bh * C * E + e;
    for (int c = 0; c < C; ++c) {
        size_t idx = base + (size_t)c * E;
        float tk = g_ksum[idx], tv = g_vsum[idx];
        g_ksum[idx] = ak;  g_vsum[idx] = av;
        ak += tk;          av += tv;
    }
}

// ---------------------------------------------------------------------------
// Pass C: in-chunk cumsum + per-row dot + ratio; emit A as fp16 (half2 store).
// ---------------------------------------------------------------------------
__global__ __launch_bounds__(256) void attn_kernel(
    const float* __restrict__ q, const float* __restrict__ k,
    const float* __restrict__ v)
{
    const int blk = blockIdx.x;
    const int bh  = blk / C;
    const int c   = blk % C;
    const int b   = bh / H;
    const int h   = bh % H;
    const int tid = threadIdx.x;

    __shared__ float ks[L * E];
    __shared__ float vs[L * E];

    const size_t base = (size_t)blk * (L * E);

    #pragma unroll
    for (int i = tid; i < (L * E) / 4; i += 256) {
        float4 kk = ((const float4*)(k + base))[i];
        kk.x = phi(kk.x); kk.y = phi(kk.y); kk.z = phi(kk.z); kk.w = phi(kk.w);
        ((float4*)ks)[i] = kk;
        ((float4*)vs)[i] = ((const float4*)(v + base))[i];
    }
    __syncthreads();

    if (tid < 64) {
        float ak = g_ksum[(size_t)blk * E + tid];
        float av = g_vsum[(size_t)blk * E + tid];
        #pragma unroll 8
        for (int i = 0; i < L; ++i) {
            ak += ks[i * E + tid]; ks[i * E + tid] = ak;
            av += vs[i * E + tid]; vs[i * E + tid] = av;
        }
    }
    __syncthreads();

    const int w    = tid >> 5;
    const int lane = tid & 31;
    const int e0   = lane * 2;
    const int n0   = c * L;
    for (int i = w * (L / 8); i < (w + 1) * (L / 8); ++i) {
        const float2 qq = *(const float2*)(q + base + (size_t)i * E + e0);
        float p = phi(qq.x) * ks[i * E + e0] + phi(qq.y) * ks[i * E + e0 + 1];
        #pragma unroll
        for (int off = 16; off; off >>= 1)
            p += __shfl_xor_sync(0xffffffffu, p, off);
        float ratio = p / (p + EPS);
        size_t ob = ((size_t)b * SEQ + n0 + i) * D + (size_t)h * E + e0;

        float2 x = { ratio * vs[i * E + e0], ratio * vs[i * E + e0 + 1] };
        *(__half2*)(g_Af + ob) = __float22half2_rn(x);
    }
}

// ---------------------------------------------------------------------------
// Pass W: split W into fp16 hi/lo (vectorized: 4 elems/thread).
// ---------------------------------------------------------------------------
__global__ __launch_bounds__(256) void wsplit_kernel(const float* __restrict__ W)
{
    int i = (blockIdx.x * 256 + threadIdx.x) * 4;
    float4 w = *(const float4*)(W + i);
    __half h0 = __float2half_rn(w.x), h1 = __float2half_rn(w.y);
    __half h2 = __float2half_rn(w.z), h3 = __float2half_rn(w.w);
    __half2 hi01; hi01.x = h0; hi01.y = h1;
    __half2 hi23; hi23.x = h2; hi23.y = h3;
    __half2 lo01, lo23;
    lo01.x = __float2half_rn(w.x - __half2float(h0));
    lo01.y = __float2half_rn(w.y - __half2float(h1));
    lo23.x = __float2half_rn(w.z - __half2float(h2));
    lo23.y = __float2half_rn(w.w - __half2float(h3));
    *(__half2*)(g_Whi + i)     = hi01;
    *(__half2*)(g_Whi + i + 2) = hi23;
    *(__half2*)(g_Wlo + i)     = lo01;
    *(__half2*)(g_Wlo + i + 2) = lo23;
}

// ---------------------------------------------------------------------------
// Pass D: mma.sync fp16 GEMM, W-split 2-term. out[M,512] = A @ W^T + bias
// BM=128, BN=256, BK=32, 512 threads / 16 warps (4m x 4n), warp tile 32x64.
// Terms: A*Whi + A*Wlo, fp32 accum in registers.
// W is [n][k] row-major -> B fragment uses NON-trans ldmatrix.
// SMEM rows padded to 80B -> conflict-free ldmatrix. 2-stage cp.async.
// ---------------------------------------------------------------------------
constexpr int BK   = 32;
constexpr int NK   = D / BK;          // 16
constexpr int RS   = 80;              // smem row stride (bytes) for 64B of data
constexpr int MTXA = 128 * RS;        // 10240
constexpr int MTXB = 256 * RS;        // 20480
constexpr int STG  = MTXA + 2 * MTXB; // 51200: A | Wh | Wl
constexpr int GEMM_DSMEM = 2 * STG;   // 102400

__device__ __forceinline__ void cp16(uint32_t dst, const void* src) {
    asm volatile("cp.async.cg.shared.global [%0], [%1], 16;"
                 :: "r"(dst), "l"(src) : "memory");
}
__device__ __forceinline__ void cp_commit() {
    asm volatile("cp.async.commit_group;" ::: "memory");
}
template<int N> __device__ __forceinline__ void cp_wait() {
    asm volatile("cp.async.wait_group %0;" :: "n"(N) : "memory");
}
__device__ __forceinline__ void ldsm4(uint32_t* r, uint32_t a) {
    asm volatile("ldmatrix.sync.aligned.m8n8.x4.shared.b16 {%0,%1,%2,%3}, [%4];"
                 : "=r"(r[0]), "=r"(r[1]), "=r"(r[2]), "=r"(r[3]) : "r"(a));
}
__device__ __forceinline__ void mma16816(float* c, const uint32_t* a,
                                         uint32_t b0, uint32_t b1) {
    asm volatile(
        "mma.sync.aligned.m16n8k16.row.col.f32.f16.f16.f32 "
        "{%0,%1,%2,%3}, {%4,%5,%6,%7}, {%8,%9}, {%0,%1,%2,%3};"
        : "+f"(c[0]), "+f"(c[1]), "+f"(c[2]), "+f"(c[3])
        : "r"(a[0]), "r"(a[1]), "r"(a[2]), "r"(a[3]), "r"(b0), "r"(b1));
}

__global__ __launch_bounds__(512, 1) void gemm_mma_kernel(
    const float* __restrict__ bias, float* __restrict__ out)
{
    extern __shared__ char sm[];
    const int tid  = threadIdx.x;
    const int lane = tid & 31;
    const int wid  = tid >> 5;      // 0..15
    const int wm   = wid & 3;       // 0..3: 32-row slab
    const int wn   = wid >> 2;      // 0..3: 64-col slab
    const int bn   = blockIdx.x;    // 0..1
    const int bm   = blockIdx.y;    // 0..127
    const uint32_t sbase = smem_u32(sm);

    auto load_stage = [&](int s, int kt) {
        const int k0 = kt * BK;
        const uint32_t d0 = sbase + s * STG;
        // A: 512 float4 chunks (128 rows x 4), one per thread
        {
            const int r = tid >> 2, c = tid & 3;
            const uint32_t so = (uint32_t)(r * RS + c * 16);
            cp16(d0 + so, g_Af + (size_t)(bm * 128 + r) * D + k0 + c * 8);
        }
        // W hi/lo: 1024 chunks each (256 rows x 4), two per thread per matrix
        #pragma unroll
        for (int hh = 0; hh < 2; ++hh) {
            const int j = tid + hh * 512;
            const int r = j >> 2, c = j & 3;
            const uint32_t so = (uint32_t)(r * RS + c * 16);
            const size_t gb = (size_t)(bn * 256 + r) * D + k0 + c * 8;
            cp16(d0 + MTXA + so,        g_Whi + gb);
            cp16(d0 + MTXA + MTXB + so, g_Wlo + gb);
        }
    };

    // ldmatrix per-lane addressing: row = lane&15, k-half = lane>>4
    const int lrow = lane & 15, lkh = lane >> 4;
    const uint32_t aoff = (uint32_t)((wm * 32 + lrow) * RS + lkh * 16);
    const uint32_t boff = (uint32_t)(MTXA + (wn * 64 + lrow) * RS + lkh * 16);

    float acc[2][8][4] = {};

    load_stage(0, 0);
    cp_commit();

    for (int kt = 0; kt < NK; ++kt) {
        const int s = kt & 1;
        if (kt + 1 < NK) { load_stage(s ^ 1, kt + 1); cp_commit(); cp_wait<1>(); }
        else             { cp_wait<0>(); }
        __syncthreads();

        const uint32_t st0 = sbase + s * STG;
        #pragma unroll
        for (int st = 0; st < 2; ++st) {        // two k16 steps per BK=32
            uint32_t af[2][4], bh[4][4], bl[4][4];
            #pragma unroll
            for (int mi = 0; mi < 2; ++mi)
                ldsm4(af[mi], st0 + aoff + mi * (16 * RS) + st * 32);
            #pragma unroll
            for (int nt = 0; nt < 4; ++nt) {
                const uint32_t a = st0 + boff + nt * (16 * RS) + st * 32;
                ldsm4(bh[nt], a);           // NON-trans: W is [n][k] row-major
                ldsm4(bl[nt], a + MTXB);
            }
            #pragma unroll
            for (int mi = 0; mi < 2; ++mi)
                #pragma unroll
                for (int nt = 0; nt < 4; ++nt) {
                    mma16816(acc[mi][nt*2+0], af[mi], bh[nt][0], bh[nt][2]);
                    mma16816(acc[mi][nt*2+1], af[mi], bh[nt][1], bh[nt][3]);
                    mma16816(acc[mi][nt*2+0], af[mi], bl[nt][0], bl[nt][2]);
                    mma16816(acc[mi][nt*2+1], af[mi], bl[nt][1], bl[nt][3]);
                }
        }
        __syncthreads();
    }

    // Epilogue: c-frag rows g, g+8; cols 2*tig, 2*tig+1
    const int g   = lane >> 2;
    const int tig = lane & 3;
    #pragma unroll
    for (int mi = 0; mi < 2; ++mi) {
        const int row0 = bm * 128 + wm * 32 + mi * 16 + g;
        #pragma unroll
        for (int nt = 0; nt < 4; ++nt)
            #pragma unroll
            for (int nh = 0; nh < 2; ++nh) {
                const float* a4 = acc[mi][nt * 2 + nh];
                const int col = bn * 256 + wn * 64 + nt * 16 + nh * 8 + tig * 2;
                const float2 bv = *(const float2*)(bias + col);
                float2 o0 = { a4[0] + bv.x, a4[1] + bv.y };
                float2 o1 = { a4[2] + bv.x, a4[3] + bv.y };
                *(float2*)(out + (size_t)row0 * D + col)       = o0;
                *(float2*)(out + (size_t)(row0 + 8) * D + col) = o1;
            }
    }
}

// ---------------------------------------------------------------------------
extern "C" void kernel_launch(void* const* d_in, const int* in_sizes, int n_in,
                              void* d_out, int out_size)
{
    const float* q    = (const float*)d_in[0];
    const float* k    = (const float*)d_in[1];
    const float* v    = (const float*)d_in[2];
    // d_in[3] = mask (unused)
    const float* W    = (const float*)d_in[4];
    const float* bias = (const float*)d_in[5];
    float* out = (float*)d_out;

    // idempotent, called every launch (no static guards)
    cudaFuncSetAttribute(gemm_mma_kernel,
                         cudaFuncAttributeMaxDynamicSharedMemorySize, GEMM_DSMEM);

    chunk_sums_kernel<<<BH * C, 256>>>(k, v);
    chunk_scan_kernel<<<BH, 64>>>();
    attn_kernel<<<BH * C, 256>>>(q, k, v);
    wsplit_kernel<<<(D * D) / 1024, 256>>>(W);
    gemm_mma_kernel<<<dim3(2, 128), 512, GEMM_DSMEM>>>(bias, out);
}

// round 7
// speedup vs baseline: 3.1212x; 1.3357x over previous
#include <cuda_runtime.h>
#include <cuda_fp16.h>
#include <cstdint>

#define EPS 1e-5f

// Problem shape (fixed by the reference)
constexpr int B   = 4;
constexpr int H   = 8;
constexpr int SEQ = 4096;
constexpr int E   = 64;
constexpr int D   = 512;          // H*E
constexpr int BH  = B * H;        // 32
constexpr int L   = 64;           // chunk length
constexpr int C   = SEQ / L;      // 64 chunks per (b,h)
constexpr int M   = B * SEQ;      // 16384 GEMM rows
constexpr int NBLK = BH * C;      // 2048 scan blocks

// Scratch (device globals — no allocation allowed)
__device__ __half g_Af[(size_t)M * D];     // A in fp16
__device__ __half g_Wh[(size_t)D * D];     // W in fp16
__device__ float g_aggk[NBLK * E];
__device__ float g_aggv[NBLK * E];
__device__ float g_inck[NBLK * E];
__device__ float g_incv[NBLK * E];
__device__ int   g_flag[NBLK];             // 0=none, 1=aggregate, 2=inclusive
__device__ int   g_vid_counter;

__device__ __forceinline__ float phi(float x) {
    return x > 0.f ? x + 1.f : __expf(x);
}

__device__ __forceinline__ uint32_t smem_u32(const void* p) {
    uint32_t a;
    asm("{ .reg .u64 t; cvta.to.shared.u64 t, %1; cvt.u32.u64 %0, t; }"
        : "=r"(a) : "l"(p));
    return a;
}

// ---------------------------------------------------------------------------
// Init: reset lookback flags + vid counter (runs every launch; graph-safe).
// ---------------------------------------------------------------------------
__global__ __launch_bounds__(1024) void init_kernel()
{
    int i = blockIdx.x * 1024 + threadIdx.x;
    if (i < NBLK) g_flag[i] = 0;
    if (i == 0)   g_vid_counter = 0;
}

// ---------------------------------------------------------------------------
// Fused single-pass scan + attention (decoupled lookback).
// grid = NBLK x 256 threads. vid via atomic counter (deadlock-free ordering),
// c-major mapping so all 32 bh chains progress in parallel.
// ---------------------------------------------------------------------------
__global__ __launch_bounds__(256) void fused_attn_kernel(
    const float* __restrict__ q, const float* __restrict__ k,
    const float* __restrict__ v)
{
    __shared__ float ks[L * E];        // 16 KB
    __shared__ float vs[L * E];        // 16 KB
    __shared__ float shk[4][64], shv[4][64];
    __shared__ float prefk[64], prefv[64];
    __shared__ int   s_vid, s_stat;

    const int tid = threadIdx.x;
    if (tid == 0) s_vid = atomicAdd(&g_vid_counter, 1);
    __syncthreads();
    const int vid = s_vid;
    const int c   = vid / BH;          // chunk index (c-major: chains advance together)
    const int bh  = vid % BH;
    const int blk = bh * C + c;        // data-layout block index
    const int b   = bh / H;
    const int h   = bh % H;
    const size_t base = (size_t)blk * (L * E);

    // ---- load + feature map ----
    #pragma unroll
    for (int i = tid; i < (L * E) / 4; i += 256) {
        float4 kk = ((const float4*)(k + base))[i];
        kk.x = phi(kk.x); kk.y = phi(kk.y); kk.z = phi(kk.z); kk.w = phi(kk.w);
        ((float4*)ks)[i] = kk;
        ((float4*)vs)[i] = ((const float4*)(v + base))[i];
    }
    __syncthreads();

    // ---- chunk aggregates ----
    {
        const int e = tid & 63, g = tid >> 6;
        float sk = 0.f, sv = 0.f;
        #pragma unroll 4
        for (int r = g * 16; r < g * 16 + 16; ++r) {
            sk += ks[r * E + e];
            sv += vs[r * E + e];
        }
        shk[g][e] = sk; shv[g][e] = sv;
    }
    __syncthreads();

    float agg = 0.f;   // tid<64: k-agg for col tid; tid in [64,128): v-agg for col tid-64
    if (tid < 64) {
        agg = shk[0][tid] + shk[1][tid] + shk[2][tid] + shk[3][tid];
        g_aggk[blk * E + tid] = agg;
        __threadfence();
    } else if (tid < 128) {
        const int e = tid - 64;
        agg = shv[0][e] + shv[1][e] + shv[2][e] + shv[3][e];
        g_aggv[blk * E + e] = agg;
        __threadfence();
    }
    __syncthreads();
    if (tid == 0) atomicExch(&g_flag[blk], 1);

    // ---- decoupled lookback: exclusive prefix ----
    float acc = 0.f;
    for (int p = c - 1; p >= 0; --p) {
        const int pblk = bh * C + p;
        __syncthreads();               // protect s_stat reuse
        if (tid == 0) {
            int f;
            do { f = atomicAdd(&g_flag[pblk], 0); } while (f == 0);
            __threadfence();           // acquire: order data reads after flag
            s_stat = f;
        }
        __syncthreads();
        const int f = s_stat;
        if (tid < 64)
            acc += (f == 2) ? g_inck[pblk * E + tid] : g_aggk[pblk * E + tid];
        else if (tid < 128)
            acc += (f == 2) ? g_incv[pblk * E + tid - 64] : g_aggv[pblk * E + tid - 64];
        if (f == 2) break;             // uniform across block
    }

    // publish inclusive; stash exclusive prefix for the scan
    if (tid < 64) {
        g_inck[blk * E + tid] = acc + agg;
        prefk[tid] = acc;
        __threadfence();
    } else if (tid < 128) {
        g_incv[blk * E + tid - 64] = acc + agg;
        prefv[tid - 64] = acc;
        __threadfence();
    }
    __syncthreads();
    if (tid == 0) atomicExch(&g_flag[blk], 2);

    // ---- in-chunk serial scan (thread t owns e-column t) ----
    if (tid < 64) {
        float ak = prefk[tid];
        float av = prefv[tid];
        #pragma unroll 8
        for (int i = 0; i < L; ++i) {
            ak += ks[i * E + tid]; ks[i * E + tid] = ak;
            av += vs[i * E + tid]; vs[i * E + tid] = av;
        }
    }
    __syncthreads();

    // ---- per-row dot + ratio + fp16 write ----
    const int w    = tid >> 5;
    const int lane = tid & 31;
    const int e0   = lane * 2;
    const int n0   = c * L;
    for (int i = w * (L / 8); i < (w + 1) * (L / 8); ++i) {
        const float2 qq = *(const float2*)(q + base + (size_t)i * E + e0);
        float p = phi(qq.x) * ks[i * E + e0] + phi(qq.y) * ks[i * E + e0 + 1];
        #pragma unroll
        for (int off = 16; off; off >>= 1)
            p += __shfl_xor_sync(0xffffffffu, p, off);
        float ratio = p / (p + EPS);
        size_t ob = ((size_t)b * SEQ + n0 + i) * D + (size_t)h * E + e0;
        float2 x = { ratio * vs[i * E + e0], ratio * vs[i * E + e0 + 1] };
        *(__half2*)(g_Af + ob) = __float22half2_rn(x);
    }
}

// ---------------------------------------------------------------------------
// W convert fp32 -> fp16 (4 elems/thread).
// ---------------------------------------------------------------------------
__global__ __launch_bounds__(256) void wconv_kernel(const float* __restrict__ W)
{
    int i = (blockIdx.x * 256 + threadIdx.x) * 4;
    float4 w = *(const float4*)(W + i);
    __half2 h01; h01.x = __float2half_rn(w.x); h01.y = __float2half_rn(w.y);
    __half2 h23; h23.x = __float2half_rn(w.z); h23.y = __float2half_rn(w.w);
    *(__half2*)(g_Wh + i)     = h01;
    *(__half2*)(g_Wh + i + 2) = h23;
}

// ---------------------------------------------------------------------------
// GEMM: out[M,512] = A @ W^T + bias, single fp16 term, fp32 accum.
// BM=128, BN=256, BK=32, 512 threads / 16 warps (4m x 4n), warp tile 32x64.
// W is [n][k] row-major -> B fragment uses NON-trans ldmatrix.
// SMEM rows padded to 80B -> conflict-free ldmatrix. 2-stage cp.async.
// ---------------------------------------------------------------------------
constexpr int BK   = 32;
constexpr int NK   = D / BK;          // 16
constexpr int RS   = 80;
constexpr int MTXA = 128 * RS;        // 10240
constexpr int MTXB = 256 * RS;        // 20480
constexpr int STG  = MTXA + MTXB;     // 30720
constexpr int GEMM_DSMEM = 2 * STG;   // 61440

__device__ __forceinline__ void cp16(uint32_t dst, const void* src) {
    asm volatile("cp.async.cg.shared.global [%0], [%1], 16;"
                 :: "r"(dst), "l"(src) : "memory");
}
__device__ __forceinline__ void cp_commit() {
    asm volatile("cp.async.commit_group;" ::: "memory");
}
template<int N> __device__ __forceinline__ void cp_wait() {
    asm volatile("cp.async.wait_group %0;" :: "n"(N) : "memory");
}
__device__ __forceinline__ void ldsm4(uint32_t* r, uint32_t a) {
    asm volatile("ldmatrix.sync.aligned.m8n8.x4.shared.b16 {%0,%1,%2,%3}, [%4];"
                 : "=r"(r[0]), "=r"(r[1]), "=r"(r[2]), "=r"(r[3]) : "r"(a));
}
__device__ __forceinline__ void mma16816(float* c, const uint32_t* a,
                                         uint32_t b0, uint32_t b1) {
    asm volatile(
        "mma.sync.aligned.m16n8k16.row.col.f32.f16.f16.f32 "
        "{%0,%1,%2,%3}, {%4,%5,%6,%7}, {%8,%9}, {%0,%1,%2,%3};"
        : "+f"(c[0]), "+f"(c[1]), "+f"(c[2]), "+f"(c[3])
        : "r"(a[0]), "r"(a[1]), "r"(a[2]), "r"(a[3]), "r"(b0), "r"(b1));
}

__global__ __launch_bounds__(512, 1) void gemm_mma_kernel(
    const float* __restrict__ bias, float* __restrict__ out)
{
    extern __shared__ char sm[];
    const int tid  = threadIdx.x;
    const int lane = tid & 31;
    const int wid  = tid >> 5;
    const int wm   = wid & 3;
    const int wn   = wid >> 2;
    const int bn   = blockIdx.x;    // 0..1
    const int bm   = blockIdx.y;    // 0..127
    const uint32_t sbase = smem_u32(sm);

    auto load_stage = [&](int s, int kt) {
        const int k0 = kt * BK;
        const uint32_t d0 = sbase + s * STG;
        {
            const int r = tid >> 2, c = tid & 3;
            const uint32_t so = (uint32_t)(r * RS + c * 16);
            cp16(d0 + so, g_Af + (size_t)(bm * 128 + r) * D + k0 + c * 8);
        }
        #pragma unroll
        for (int hh = 0; hh < 2; ++hh) {
            const int j = tid + hh * 512;
            const int r = j >> 2, c = j & 3;
            const uint32_t so = (uint32_t)(r * RS + c * 16);
            cp16(d0 + MTXA + so, g_Wh + (size_t)(bn * 256 + r) * D + k0 + c * 8);
        }
    };

    const int lrow = lane & 15, lkh = lane >> 4;
    const uint32_t aoff = (uint32_t)((wm * 32 + lrow) * RS + lkh * 16);
    const uint32_t boff = (uint32_t)(MTXA + (wn * 64 + lrow) * RS + lkh * 16);

    float acc[2][8][4] = {};

    load_stage(0, 0);
    cp_commit();

    for (int kt = 0; kt < NK; ++kt) {
        const int s = kt & 1;
        if (kt + 1 < NK) { load_stage(s ^ 1, kt + 1); cp_commit(); cp_wait<1>(); }
        else             { cp_wait<0>(); }
        __syncthreads();

        const uint32_t st0 = sbase + s * STG;
        #pragma unroll
        for (int st = 0; st < 2; ++st) {
            uint32_t af[2][4], bf[4][4];
            #pragma unroll
            for (int mi = 0; mi < 2; ++mi)
                ldsm4(af[mi], st0 + aoff + mi * (16 * RS) + st * 32);
            #pragma unroll
            for (int nt = 0; nt < 4; ++nt)
                ldsm4(bf[nt], st0 + boff + nt * (16 * RS) + st * 32);
            #pragma unroll
            for (int mi = 0; mi < 2; ++mi)
                #pragma unroll
                for (int nt = 0; nt < 4; ++nt) {
                    mma16816(acc[mi][nt*2+0], af[mi], bf[nt][0], bf[nt][2]);
                    mma16816(acc[mi][nt*2+1], af[mi], bf[nt][1], bf[nt][3]);
                }
        }
        __syncthreads();
    }

    const int g   = lane >> 2;
    const int tig = lane & 3;
    #pragma unroll
    for (int mi = 0; mi < 2; ++mi) {
        const int row0 = bm * 128 + wm * 32 + mi * 16 + g;
        #pragma unroll
        for (int nt = 0; nt < 4; ++nt)
            #pragma unroll
            for (int nh = 0; nh < 2; ++nh) {
                const float* a4 = acc[mi][nt * 2 + nh];
                const int col = bn * 256 + wn * 64 + nt * 16 + nh * 8 + tig * 2;
                const float2 bv = *(const float2*)(bias + col);
                float2 o0 = { a4[0] + bv.x, a4[1] + bv.y };
                float2 o1 = { a4[2] + bv.x, a4[3] + bv.y };
                *(float2*)(out + (size_t)row0 * D + col)       = o0;
                *(float2*)(out + (size_t)(row0 + 8) * D + col) = o1;
            }
    }
}

// ---------------------------------------------------------------------------
extern "C" void kernel_launch(void* const* d_in, const int* in_sizes, int n_in,
                              void* d_out, int out_size)
{
    const float* q    = (const float*)d_in[0];
    const float* k    = (const float*)d_in[1];
    const float* v    = (const float*)d_in[2];
    // d_in[3] = mask (unused)
    const float* W    = (const float*)d_in[4];
    const float* bias = (const float*)d_in[5];
    float* out = (float*)d_out;

    cudaFuncSetAttribute(gemm_mma_kernel,
                         cudaFuncAttributeMaxDynamicSharedMemorySize, GEMM_DSMEM);

    init_kernel<<<(NBLK + 1023) / 1024, 1024>>>();
    fused_attn_kernel<<<NBLK, 256>>>(q, k, v);
    wconv_kernel<<<(D * D) / 1024, 256>>>(W);
    gemm_mma_kernel<<<dim3(2, 128), 512, GEMM_DSMEM>>>(bias, out);
}

// round 8
// speedup vs baseline: 3.5398x; 1.1341x over previous
#include <cuda_runtime.h>
#include <cuda_fp16.h>
#include <cstdint>

#define EPS 1e-5f

constexpr int B   = 4;
constexpr int H   = 8;
constexpr int SEQ = 4096;
constexpr int E   = 64;
constexpr int D   = 512;          // H*E
constexpr int BH  = B * H;        // 32
constexpr int L   = 64;           // chunk length
constexpr int C   = SEQ / L;      // 64 chunks per (b,h)
constexpr int M   = B * SEQ;      // 16384 GEMM rows
constexpr int NBLK = BH * C;      // 2048 scan blocks

// Scratch (device globals — no allocation allowed)
__device__ __half g_Af[(size_t)M * D];     // A in fp16
__device__ __half g_Wh[(size_t)D * D];     // W in fp16
__device__ float g_aggk[NBLK * E];
__device__ float g_aggv[NBLK * E];
__device__ float g_inck[NBLK * E];
__device__ float g_incv[NBLK * E];
__device__ int   g_flag[NBLK];             // 0=none, 1=aggregate, 2=inclusive
__device__ int   g_vid_counter;

__device__ __forceinline__ float phi(float x) {
    return x > 0.f ? x + 1.f : __expf(x);
}

__device__ __forceinline__ uint32_t smem_u32(const void* p) {
    uint32_t a;
    asm("{ .reg .u64 t; cvta.to.shared.u64 t, %1; cvt.u32.u64 %0, t; }"
        : "=r"(a) : "l"(p));
    return a;
}

// ---------------------------------------------------------------------------
// Init: reset lookback flags + vid counter (runs every launch; graph-safe).
// ---------------------------------------------------------------------------
__global__ __launch_bounds__(1024) void init_kernel()
{
    int i = blockIdx.x * 1024 + threadIdx.x;
    if (i < NBLK) g_flag[i] = 0;
    if (i == 0)   g_vid_counter = 0;
}

// ---------------------------------------------------------------------------
// Fused single-pass scan + attention (decoupled lookback).
// q prefetched to registers; warp-0-only lookback; split k/v in-chunk scans.
// ---------------------------------------------------------------------------
__global__ __launch_bounds__(256) void fused_attn_kernel(
    const float* __restrict__ q, const float* __restrict__ k,
    const float* __restrict__ v)
{
    __shared__ float ks[L * E];        // 16 KB
    __shared__ float vs[L * E];        // 16 KB
    __shared__ float shk[4][64], shv[4][64];
    __shared__ float prefk[64], prefv[64];
    __shared__ int   s_vid;

    const int tid  = threadIdx.x;
    const int w    = tid >> 5;
    const int lane = tid & 31;
    const int e0   = lane * 2;

    if (tid == 0) s_vid = atomicAdd(&g_vid_counter, 1);
    __syncthreads();
    const int vid = s_vid;
    const int c   = vid / BH;          // c-major: all 32 bh chains advance together
    const int bh  = vid % BH;
    const int blk = bh * C + c;
    const int b   = bh / H;
    const int h   = bh % H;
    const size_t base = (size_t)blk * (L * E);

    // ---- prefetch q rows this thread will dot (in flight during everything) ----
    float2 qreg[8];
    #pragma unroll
    for (int r = 0; r < 8; ++r)
        qreg[r] = *(const float2*)(q + base + (size_t)(w * 8 + r) * E + e0);

    // ---- load k,v + feature map ----
    #pragma unroll
    for (int i = tid; i < (L * E) / 4; i += 256) {
        float4 kk = ((const float4*)(k + base))[i];
        kk.x = phi(kk.x); kk.y = phi(kk.y); kk.z = phi(kk.z); kk.w = phi(kk.w);
        ((float4*)ks)[i] = kk;
        ((float4*)vs)[i] = ((const float4*)(v + base))[i];
    }
    __syncthreads();

    // ---- partial chunk aggregates ----
    {
        const int e = tid & 63, g = tid >> 6;
        float sk = 0.f, sv = 0.f;
        #pragma unroll 4
        for (int r = g * 16; r < g * 16 + 16; ++r) {
            sk += ks[r * E + e];
            sv += vs[r * E + e];
        }
        shk[g][e] = sk; shv[g][e] = sv;
    }
    __syncthreads();

    // publish aggregate (tid<128: 64 k-cols + 64 v-cols)
    if (tid < 64) {
        g_aggk[blk * E + tid] = shk[0][tid] + shk[1][tid] + shk[2][tid] + shk[3][tid];
    } else if (tid < 128) {
        const int e = tid - 64;
        g_aggv[blk * E + e] = shv[0][e] + shv[1][e] + shv[2][e] + shv[3][e];
    }
    __threadfence();
    __syncthreads();
    if (tid == 0) atomicExch(&g_flag[blk], 1);

    // ---- warp-0-only decoupled lookback (no block syncs in the loop) ----
    if (w == 0) {
        float aK0 = 0.f, aK1 = 0.f, aV0 = 0.f, aV1 = 0.f;
        for (int p = c - 1; p >= 0; --p) {
            const int pblk = bh * C + p;
            int f = 0;
            if (lane == 0) {
                do { f = atomicAdd(&g_flag[pblk], 0); } while (f == 0);
            }
            f = __shfl_sync(0xffffffffu, f, 0);
            __threadfence();           // acquire: data reads after observed flag
            const float* srcK = (f == 2) ? g_inck : g_aggk;
            const float* srcV = (f == 2) ? g_incv : g_aggv;
            aK0 += srcK[pblk * E + lane];
            aK1 += srcK[pblk * E + lane + 32];
            aV0 += srcV[pblk * E + lane];
            aV1 += srcV[pblk * E + lane + 32];
            if (f == 2) break;
        }
        // inclusive = exclusive + own aggregate (recomputed from smem partials)
        const float gK0 = shk[0][lane] + shk[1][lane] + shk[2][lane] + shk[3][lane];
        const float gK1 = shk[0][lane+32] + shk[1][lane+32] + shk[2][lane+32] + shk[3][lane+32];
        const float gV0 = shv[0][lane] + shv[1][lane] + shv[2][lane] + shv[3][lane];
        const float gV1 = shv[0][lane+32] + shv[1][lane+32] + shv[2][lane+32] + shv[3][lane+32];
        g_inck[blk * E + lane]      = aK0 + gK0;
        g_inck[blk * E + lane + 32] = aK1 + gK1;
        g_incv[blk * E + lane]      = aV0 + gV0;
        g_incv[blk * E + lane + 32] = aV1 + gV1;
        __threadfence();
        if (lane == 0) atomicExch(&g_flag[blk], 2);
        prefk[lane]      = aK0;  prefk[lane + 32] = aK1;
        prefv[lane]      = aV0;  prefv[lane + 32] = aV1;
    }
    __syncthreads();

    // ---- in-chunk serial scans: tid<64 k-col tid; tid in [64,128) v-col ----
    if (tid < 64) {
        float ak = prefk[tid];
        #pragma unroll 8
        for (int i = 0; i < L; ++i) { ak += ks[i * E + tid]; ks[i * E + tid] = ak; }
    } else if (tid < 128) {
        const int e = tid - 64;
        float av = prefv[e];
        #pragma unroll 8
        for (int i = 0; i < L; ++i) { av += vs[i * E + e]; vs[i * E + e] = av; }
    }
    __syncthreads();

    // ---- per-row dot + ratio + fp16 write ----
    const int n0 = c * L;
    #pragma unroll
    for (int r = 0; r < 8; ++r) {
        const int i = w * 8 + r;
        float p = phi(qreg[r].x) * ks[i * E + e0] + phi(qreg[r].y) * ks[i * E + e0 + 1];
        #pragma unroll
        for (int off = 16; off; off >>= 1)
            p += __shfl_xor_sync(0xffffffffu, p, off);
        float ratio = p / (p + EPS);
        size_t ob = ((size_t)b * SEQ + n0 + i) * D + (size_t)h * E + e0;
        float2 x = { ratio * vs[i * E + e0], ratio * vs[i * E + e0 + 1] };
        *(__half2*)(g_Af + ob) = __float22half2_rn(x);
    }
}

// ---------------------------------------------------------------------------
// W convert fp32 -> fp16 (4 elems/thread).
// ---------------------------------------------------------------------------
__global__ __launch_bounds__(256) void wconv_kernel(const float* __restrict__ W)
{
    int i = (blockIdx.x * 256 + threadIdx.x) * 4;
    float4 w = *(const float4*)(W + i);
    __half2 h01; h01.x = __float2half_rn(w.x); h01.y = __float2half_rn(w.y);
    __half2 h23; h23.x = __float2half_rn(w.z); h23.y = __float2half_rn(w.w);
    *(__half2*)(g_Wh + i)     = h01;
    *(__half2*)(g_Wh + i + 2) = h23;
}

// ---------------------------------------------------------------------------
// GEMM: out[M,512] = A @ W^T + bias, fp16 MMA, fp32 accum.
// BM=64, BN=256, BK=32, 256 threads / 8 warps (2m x 4n), warp tile 32x64.
// 2 CTAs/SM (launch_bounds(256,2)) to hide barrier + ldmatrix latency.
// W is [n][k] row-major -> B fragment uses NON-trans ldmatrix.
// SMEM rows padded to 80B; 2-stage cp.async.
// ---------------------------------------------------------------------------
constexpr int BK   = 32;
constexpr int NK   = D / BK;          // 16
constexpr int RS   = 80;
constexpr int MTXA = 64 * RS;         // 5120
constexpr int MTXB = 256 * RS;        // 20480
constexpr int STG  = MTXA + MTXB;     // 25600
constexpr int GEMM_DSMEM = 2 * STG;   // 51200

__device__ __forceinline__ void cp16(uint32_t dst, const void* src) {
    asm volatile("cp.async.cg.shared.global [%0], [%1], 16;"
                 :: "r"(dst), "l"(src) : "memory");
}
__device__ __forceinline__ void cp_commit() {
    asm volatile("cp.async.commit_group;" ::: "memory");
}
template<int N> __device__ __forceinline__ void cp_wait() {
    asm volatile("cp.async.wait_group %0;" :: "n"(N) : "memory");
}
__device__ __forceinline__ void ldsm4(uint32_t* r, uint32_t a) {
    asm volatile("ldmatrix.sync.aligned.m8n8.x4.shared.b16 {%0,%1,%2,%3}, [%4];"
                 : "=r"(r[0]), "=r"(r[1]), "=r"(r[2]), "=r"(r[3]) : "r"(a));
}
__device__ __forceinline__ void mma16816(float* c, const uint32_t* a,
                                         uint32_t b0, uint32_t b1) {
    asm volatile(
        "mma.sync.aligned.m16n8k16.row.col.f32.f16.f16.f32 "
        "{%0,%1,%2,%3}, {%4,%5,%6,%7}, {%8,%9}, {%0,%1,%2,%3};"
        : "+f"(c[0]), "+f"(c[1]), "+f"(c[2]), "+f"(c[3])
        : "r"(a[0]), "r"(a[1]), "r"(a[2]), "r"(a[3]), "r"(b0), "r"(b1));
}

__global__ __launch_bounds__(256, 2) void gemm_mma_kernel(
    const float* __restrict__ bias, float* __restrict__ out)
{
    extern __shared__ char sm[];
    const int tid  = threadIdx.x;
    const int lane = tid & 31;
    const int wid  = tid >> 5;      // 0..7
    const int wm   = wid & 1;       // 0..1: 32-row slab
    const int wn   = wid >> 1;      // 0..3: 64-col slab
    const int bn   = blockIdx.x;    // 0..1
    const int bm   = blockIdx.y;    // 0..255
    const uint32_t sbase = smem_u32(sm);

    auto load_stage = [&](int s, int kt) {
        const int k0 = kt * BK;
        const uint32_t d0 = sbase + s * STG;
        // A: 256 float4 chunks (64 rows x 4), one per thread
        {
            const int r = tid >> 2, cc = tid & 3;
            const uint32_t so = (uint32_t)(r * RS + cc * 16);
            cp16(d0 + so, g_Af + (size_t)(bm * 64 + r) * D + k0 + cc * 8);
        }
        // W: 1024 chunks (256 rows x 4), four per thread
        #pragma unroll
        for (int hh = 0; hh < 4; ++hh) {
            const int j = tid + hh * 256;
            const int r = j >> 2, cc = j & 3;
            const uint32_t so = (uint32_t)(r * RS + cc * 16);
            cp16(d0 + MTXA + so, g_Wh + (size_t)(bn * 256 + r) * D + k0 + cc * 8);
        }
    };

    const int lrow = lane & 15, lkh = lane >> 4;
    const uint32_t aoff = (uint32_t)((wm * 32 + lrow) * RS + lkh * 16);
    const uint32_t boff = (uint32_t)(MTXA + (wn * 64 + lrow) * RS + lkh * 16);

    float acc[2][8][4] = {};

    load_stage(0, 0);
    cp_commit();

    for (int kt = 0; kt < NK; ++kt) {
        const int s = kt & 1;
        if (kt + 1 < NK) { load_stage(s ^ 1, kt + 1); cp_commit(); cp_wait<1>(); }
        else             { cp_wait<0>(); }
        __syncthreads();

        const uint32_t st0 = sbase + s * STG;
        #pragma unroll
        for (int st = 0; st < 2; ++st) {
            uint32_t af[2][4], bf[4][4];
            #pragma unroll
            for (int mi = 0; mi < 2; ++mi)
                ldsm4(af[mi], st0 + aoff + mi * (16 * RS) + st * 32);
            #pragma unroll
            for (int nt = 0; nt < 4; ++nt)
                ldsm4(bf[nt], st0 + boff + nt * (16 * RS) + st * 32);
            #pragma unroll
            for (int mi = 0; mi < 2; ++mi)
                #pragma unroll
                for (int nt = 0; nt < 4; ++nt) {
                    mma16816(acc[mi][nt*2+0], af[mi], bf[nt][0], bf[nt][2]);
                    mma16816(acc[mi][nt*2+1], af[mi], bf[nt][1], bf[nt][3]);
                }
        }
        __syncthreads();
    }

    const int g   = lane >> 2;
    const int tig = lane & 3;
    #pragma unroll
    for (int mi = 0; mi < 2; ++mi) {
        const int row0 = bm * 64 + wm * 32 + mi * 16 + g;
        #pragma unroll
        for (int nt = 0; nt < 4; ++nt)
            #pragma unroll
            for (int nh = 0; nh < 2; ++nh) {
                const float* a4 = acc[mi][nt * 2 + nh];
                const int col = bn * 256 + wn * 64 + nt * 16 + nh * 8 + tig * 2;
                const float2 bv = *(const float2*)(bias + col);
                float2 o0 = { a4[0] + bv.x, a4[1] + bv.y };
                float2 o1 = { a4[2] + bv.x, a4[3] + bv.y };
                *(float2*)(out + (size_t)row0 * D + col)       = o0;
                *(float2*)(out + (size_t)(row0 + 8) * D + col) = o1;
            }
    }
}

// ---------------------------------------------------------------------------
extern "C" void kernel_launch(void* const* d_in, const int* in_sizes, int n_in,
                              void* d_out, int out_size)
{
    const float* q    = (const float*)d_in[0];
    const float* k    = (const float*)d_in[1];
    const float* v    = (const float*)d_in[2];
    // d_in[3] = mask (unused)
    const float* W    = (const float*)d_in[4];
    const float* bias = (const float*)d_in[5];
    float* out = (float*)d_out;

    cudaFuncSetAttribute(gemm_mma_kernel,
                         cudaFuncAttributeMaxDynamicSharedMemorySize, GEMM_DSMEM);

    init_kernel<<<(NBLK + 1023) / 1024, 1024>>>();
    fused_attn_kernel<<<NBLK, 256>>>(q, k, v);
    wconv_kernel<<<(D * D) / 1024, 256>>>(W);
    gemm_mma_kernel<<<dim3(2, 256), 256, GEMM_DSMEM>>>(bias, out);
}

// round 9
// speedup vs baseline: 3.6441x; 1.0295x over previous
#include <cuda_runtime.h>
#include <cuda_fp16.h>
#include <cstdint>

#define EPS 1e-5f

constexpr int B   = 4;
constexpr int H   = 8;
constexpr int SEQ = 4096;
constexpr int E   = 64;
constexpr int D   = 512;          // H*E
constexpr int BH  = B * H;        // 32
constexpr int L   = 64;           // chunk length
constexpr int C   = SEQ / L;      // 64 chunks per (b,h)
constexpr int M   = B * SEQ;      // 16384 GEMM rows
constexpr int NBLK = BH * C;      // 2048 scan blocks

// Scratch (device globals — no allocation allowed)
__device__ __half g_Af[(size_t)M * D];     // A in fp16
__device__ __half g_Wh[(size_t)D * D];     // W in fp16
__device__ float g_aggk[NBLK * E];
__device__ float g_aggv[NBLK * E];
__device__ float g_inck[NBLK * E];
__device__ float g_incv[NBLK * E];
__device__ int   g_flag[NBLK];             // 0=none, 1=aggregate, 2=inclusive
__device__ int   g_vid_counter;

__device__ __forceinline__ float phi(float x) {
    return x > 0.f ? x + 1.f : __expf(x);
}

__device__ __forceinline__ uint32_t smem_u32(const void* p) {
    uint32_t a;
    asm("{ .reg .u64 t; cvta.to.shared.u64 t, %1; cvt.u32.u64 %0, t; }"
        : "=r"(a) : "l"(p));
    return a;
}

// ---------------------------------------------------------------------------
// Init + W convert fused (one launch): reset flags/counter, W fp32->fp16.
// grid = 256 x 256 threads; thread j converts W[4j..4j+3].
// ---------------------------------------------------------------------------
__global__ __launch_bounds__(256) void init_wconv_kernel(const float* __restrict__ W)
{
    const int t = blockIdx.x * 256 + threadIdx.x;   // 0..65535
    if (t < NBLK) g_flag[t] = 0;
    if (t == 0)   g_vid_counter = 0;

    const int i = t * 4;
    float4 w = *(const float4*)(W + i);
    __half2 h01; h01.x = __float2half_rn(w.x); h01.y = __float2half_rn(w.y);
    __half2 h23; h23.x = __float2half_rn(w.z); h23.y = __float2half_rn(w.w);
    *(__half2*)(g_Wh + i)     = h01;
    *(__half2*)(g_Wh + i + 2) = h23;
}

// ---------------------------------------------------------------------------
// Fused single-pass scan + attention (decoupled lookback).
// q prefetched to registers; warp-0-only lookback; split k/v in-chunk scans.
// ---------------------------------------------------------------------------
__global__ __launch_bounds__(256) void fused_attn_kernel(
    const float* __restrict__ q, const float* __restrict__ k,
    const float* __restrict__ v)
{
    __shared__ float ks[L * E];        // 16 KB
    __shared__ float vs[L * E];        // 16 KB
    __shared__ float shk[4][64], shv[4][64];
    __shared__ float prefk[64], prefv[64];
    __shared__ int   s_vid;

    const int tid  = threadIdx.x;
    const int w    = tid >> 5;
    const int lane = tid & 31;
    const int e0   = lane * 2;

    if (tid == 0) s_vid = atomicAdd(&g_vid_counter, 1);
    __syncthreads();
    const int vid = s_vid;
    const int c   = vid / BH;          // c-major: all 32 bh chains advance together
    const int bh  = vid % BH;
    const int blk = bh * C + c;
    const int b   = bh / H;
    const int h   = bh % H;
    const size_t base = (size_t)blk * (L * E);

    // ---- prefetch q rows this thread will dot ----
    float2 qreg[8];
    #pragma unroll
    for (int r = 0; r < 8; ++r)
        qreg[r] = *(const float2*)(q + base + (size_t)(w * 8 + r) * E + e0);

    // ---- load k,v + feature map ----
    #pragma unroll
    for (int i = tid; i < (L * E) / 4; i += 256) {
        float4 kk = ((const float4*)(k + base))[i];
        kk.x = phi(kk.x); kk.y = phi(kk.y); kk.z = phi(kk.z); kk.w = phi(kk.w);
        ((float4*)ks)[i] = kk;
        ((float4*)vs)[i] = ((const float4*)(v + base))[i];
    }
    __syncthreads();

    // ---- partial chunk aggregates ----
    {
        const int e = tid & 63, g = tid >> 6;
        float sk = 0.f, sv = 0.f;
        #pragma unroll 4
        for (int r = g * 16; r < g * 16 + 16; ++r) {
            sk += ks[r * E + e];
            sv += vs[r * E + e];
        }
        shk[g][e] = sk; shv[g][e] = sv;
    }
    __syncthreads();

    // publish aggregate (tid<128: 64 k-cols + 64 v-cols)
    if (tid < 64) {
        g_aggk[blk * E + tid] = shk[0][tid] + shk[1][tid] + shk[2][tid] + shk[3][tid];
    } else if (tid < 128) {
        const int e = tid - 64;
        g_aggv[blk * E + e] = shv[0][e] + shv[1][e] + shv[2][e] + shv[3][e];
    }
    __threadfence();
    __syncthreads();
    if (tid == 0) atomicExch(&g_flag[blk], 1);

    // ---- warp-0-only decoupled lookback (no block syncs in the loop) ----
    if (w == 0) {
        float aK0 = 0.f, aK1 = 0.f, aV0 = 0.f, aV1 = 0.f;
        for (int p = c - 1; p >= 0; --p) {
            const int pblk = bh * C + p;
            int f = 0;
            if (lane == 0) {
                do { f = atomicAdd(&g_flag[pblk], 0); } while (f == 0);
            }
            f = __shfl_sync(0xffffffffu, f, 0);
            __threadfence();           // acquire: data reads after observed flag
            const float* srcK = (f == 2) ? g_inck : g_aggk;
            const float* srcV = (f == 2) ? g_incv : g_aggv;
            aK0 += srcK[pblk * E + lane];
            aK1 += srcK[pblk * E + lane + 32];
            aV0 += srcV[pblk * E + lane];
            aV1 += srcV[pblk * E + lane + 32];
            if (f == 2) break;
        }
        const float gK0 = shk[0][lane] + shk[1][lane] + shk[2][lane] + shk[3][lane];
        const float gK1 = shk[0][lane+32] + shk[1][lane+32] + shk[2][lane+32] + shk[3][lane+32];
        const float gV0 = shv[0][lane] + shv[1][lane] + shv[2][lane] + shv[3][lane];
        const float gV1 = shv[0][lane+32] + shv[1][lane+32] + shv[2][lane+32] + shv[3][lane+32];
        g_inck[blk * E + lane]      = aK0 + gK0;
        g_inck[blk * E + lane + 32] = aK1 + gK1;
        g_incv[blk * E + lane]      = aV0 + gV0;
        g_incv[blk * E + lane + 32] = aV1 + gV1;
        __threadfence();
        if (lane == 0) atomicExch(&g_flag[blk], 2);
        prefk[lane]      = aK0;  prefk[lane + 32] = aK1;
        prefv[lane]      = aV0;  prefv[lane + 32] = aV1;
    }
    __syncthreads();

    // ---- in-chunk serial scans: tid<64 k-col; tid in [64,128) v-col ----
    if (tid < 64) {
        float ak = prefk[tid];
        #pragma unroll 8
        for (int i = 0; i < L; ++i) { ak += ks[i * E + tid]; ks[i * E + tid] = ak; }
    } else if (tid < 128) {
        const int e = tid - 64;
        float av = prefv[e];
        #pragma unroll 8
        for (int i = 0; i < L; ++i) { av += vs[i * E + e]; vs[i * E + e] = av; }
    }
    __syncthreads();

    // ---- per-row dot + ratio + fp16 write ----
    const int n0 = c * L;
    #pragma unroll
    for (int r = 0; r < 8; ++r) {
        const int i = w * 8 + r;
        float p = phi(qreg[r].x) * ks[i * E + e0] + phi(qreg[r].y) * ks[i * E + e0 + 1];
        #pragma unroll
        for (int off = 16; off; off >>= 1)
            p += __shfl_xor_sync(0xffffffffu, p, off);
        float ratio = p / (p + EPS);
        size_t ob = ((size_t)b * SEQ + n0 + i) * D + (size_t)h * E + e0;
        float2 x = { ratio * vs[i * E + e0], ratio * vs[i * E + e0 + 1] };
        *(__half2*)(g_Af + ob) = __float22half2_rn(x);
    }
}

// ---------------------------------------------------------------------------
// GEMM: out[M,512] = A @ W^T + bias, fp16 MMA, fp32 accum.
// BM=64, BN=256, BK=32, 256 threads / 8 warps (2m x 4n), warp tile 32x64.
// 4-stage cp.async pipeline (prefetch distance 3), ONE __syncthreads/iter,
// always-commit so cp_wait<2> exactly drains the stage being consumed.
// 2 CTAs/SM. W is [n][k] row-major -> NON-trans ldmatrix for B.
// ---------------------------------------------------------------------------
constexpr int BK     = 32;
constexpr int NK     = D / BK;        // 16
constexpr int NSTAGE = 4;
constexpr int RS     = 80;
constexpr int MTXA   = 64 * RS;       // 5120
constexpr int MTXB   = 256 * RS;      // 20480
constexpr int STG    = MTXA + MTXB;   // 25600
constexpr int GEMM_DSMEM = NSTAGE * STG;  // 102400

__device__ __forceinline__ void cp16(uint32_t dst, const void* src) {
    asm volatile("cp.async.cg.shared.global [%0], [%1], 16;"
                 :: "r"(dst), "l"(src) : "memory");
}
__device__ __forceinline__ void cp_commit() {
    asm volatile("cp.async.commit_group;" ::: "memory");
}
template<int N> __device__ __forceinline__ void cp_wait() {
    asm volatile("cp.async.wait_group %0;" :: "n"(N) : "memory");
}
__device__ __forceinline__ void ldsm4(uint32_t* r, uint32_t a) {
    asm volatile("ldmatrix.sync.aligned.m8n8.x4.shared.b16 {%0,%1,%2,%3}, [%4];"
                 : "=r"(r[0]), "=r"(r[1]), "=r"(r[2]), "=r"(r[3]) : "r"(a));
}
__device__ __forceinline__ void mma16816(float* c, const uint32_t* a,
                                         uint32_t b0, uint32_t b1) {
    asm volatile(
        "mma.sync.aligned.m16n8k16.row.col.f32.f16.f16.f32 "
        "{%0,%1,%2,%3}, {%4,%5,%6,%7}, {%8,%9}, {%0,%1,%2,%3};"
        : "+f"(c[0]), "+f"(c[1]), "+f"(c[2]), "+f"(c[3])
        : "r"(a[0]), "r"(a[1]), "r"(a[2]), "r"(a[3]), "r"(b0), "r"(b1));
}

__global__ __launch_bounds__(256, 2) void gemm_mma_kernel(
    const float* __restrict__ bias, float* __restrict__ out)
{
    extern __shared__ char sm[];
    const int tid  = threadIdx.x;
    const int lane = tid & 31;
    const int wid  = tid >> 5;      // 0..7
    const int wm   = wid & 1;       // 0..1: 32-row slab
    const int wn   = wid >> 1;      // 0..3: 64-col slab
    const int bn   = blockIdx.x;    // 0..1
    const int bm   = blockIdx.y;    // 0..255
    const uint32_t sbase = smem_u32(sm);

    auto load_stage = [&](int s, int kt) {
        const int k0 = kt * BK;
        const uint32_t d0 = sbase + s * STG;
        {
            const int r = tid >> 2, cc = tid & 3;
            const uint32_t so = (uint32_t)(r * RS + cc * 16);
            cp16(d0 + so, g_Af + (size_t)(bm * 64 + r) * D + k0 + cc * 8);
        }
        #pragma unroll
        for (int hh = 0; hh < 4; ++hh) {
            const int j = tid + hh * 256;
            const int r = j >> 2, cc = j & 3;
            const uint32_t so = (uint32_t)(r * RS + cc * 16);
            cp16(d0 + MTXA + so, g_Wh + (size_t)(bn * 256 + r) * D + k0 + cc * 8);
        }
    };

    const int lrow = lane & 15, lkh = lane >> 4;
    const uint32_t aoff = (uint32_t)((wm * 32 + lrow) * RS + lkh * 16);
    const uint32_t boff = (uint32_t)(MTXA + (wn * 64 + lrow) * RS + lkh * 16);

    float acc[2][8][4] = {};

    // prologue: 3 stages in flight
    #pragma unroll
    for (int p = 0; p < NSTAGE - 1; ++p) { load_stage(p, p); cp_commit(); }

    for (int kt = 0; kt < NK; ++kt) {
        cp_wait<NSTAGE - 2>();         // stage kt complete (2 groups may pend)
        __syncthreads();               // all warps done with stage being refilled

        const uint32_t st0 = sbase + (kt & (NSTAGE - 1)) * STG;
        #pragma unroll
        for (int st = 0; st < 2; ++st) {
            uint32_t af[2][4], bf[4][4];
            #pragma unroll
            for (int mi = 0; mi < 2; ++mi)
                ldsm4(af[mi], st0 + aoff + mi * (16 * RS) + st * 32);
            #pragma unroll
            for (int nt = 0; nt < 4; ++nt)
                ldsm4(bf[nt], st0 + boff + nt * (16 * RS) + st * 32);
            #pragma unroll
            for (int mi = 0; mi < 2; ++mi)
                #pragma unroll
                for (int nt = 0; nt < 4; ++nt) {
                    mma16816(acc[mi][nt*2+0], af[mi], bf[nt][0], bf[nt][2]);
                    mma16816(acc[mi][nt*2+1], af[mi], bf[nt][1], bf[nt][3]);
                }
        }

        if (kt + NSTAGE - 1 < NK)
            load_stage((kt + NSTAGE - 1) & (NSTAGE - 1), kt + NSTAGE - 1);
        cp_commit();                   // always commit (empty groups keep count)
    }

    const int g   = lane >> 2;
    const int tig = lane & 3;
    #pragma unroll
    for (int mi = 0; mi < 2; ++mi) {
        const int row0 = bm * 64 + wm * 32 + mi * 16 + g;
        #pragma unroll
        for (int nt = 0; nt < 4; ++nt)
            #pragma unroll
            for (int nh = 0; nh < 2; ++nh) {
                const float* a4 = acc[mi][nt * 2 + nh];
                const int col = bn * 256 + wn * 64 + nt * 16 + nh * 8 + tig * 2;
                const float2 bv = *(const float2*)(bias + col);
                float2 o0 = { a4[0] + bv.x, a4[1] + bv.y };
                float2 o1 = { a4[2] + bv.x, a4[3] + bv.y };
                *(float2*)(out + (size_t)row0 * D + col)       = o0;
                *(float2*)(out + (size_t)(row0 + 8) * D + col) = o1;
            }
    }
}

// ---------------------------------------------------------------------------
extern "C" void kernel_launch(void* const* d_in, const int* in_sizes, int n_in,
                              void* d_out, int out_size)
{
    const float* q    = (const float*)d_in[0];
    const float* k    = (const float*)d_in[1];
    const float* v    = (const float*)d_in[2];
    // d_in[3] = mask (unused)
    const float* W    = (const float*)d_in[4];
    const float* bias = (const float*)d_in[5];
    float* out = (float*)d_out;

    cudaFuncSetAttribute(gemm_mma_kernel,
                         cudaFuncAttributeMaxDynamicSharedMemorySize, GEMM_DSMEM);

    init_wconv_kernel<<<(D * D) / 1024, 256>>>(W);
    fused_attn_kernel<<<NBLK, 256>>>(q, k, v);
    gemm_mma_kernel<<<dim3(2, 256), 256, GEMM_DSMEM>>>(bias, out);
}